// round 16
// baseline (speedup 1.0000x reference)
#include <cuda_runtime.h>
#include <cuda_fp16.h>
#include <cstdint>

#define NPOS 112
#define TPB  36
#define PMMA 96
#define NTILES 12           // PMMA/8
#define SM_UV    49152      // fp16 fragment act buffer is [0, 49152)
#define UVSTRIDE 65
#define SM_BUFA  182272     // FFMA act buffers, 256 x FSTRIDE fp32 each
#define SM_BUFB  202752
#define FSTRIDE  20
#define SMEM_TOTAL 223232

__device__ __align__(1024) uint32_t g_Wh[3 * 32768];  // fp16 MMA fragments
__device__ float g_U[32 * 256 * 64];
__device__ float g_V[32 * 256 * 64];
__device__ float g_WtT[3 * 65536];                    // fp32 W transposed [l][k][o]

__device__ __forceinline__ uint32_t faddr16(int k, int p) {
    return (((((uint32_t)(k >> 4) * NTILES + (p >> 3)) * 64
            + ((p & 7) * 4 + ((k >> 1) & 3)) * 2 + ((k >> 3) & 1)) << 2)
            + ((k & 1) << 1));
}

__global__ __launch_bounds__(512) void prologue_kernel(
    const float* __restrict__ x,
    const float* __restrict__ W1, const float* __restrict__ W2,
    const float* __restrict__ W3)
{
    if (blockIdx.x < 192) {            // W -> fp16 fragment-major
        int i = blockIdx.x * 512 + threadIdx.x;
        int reg = i & 3, lane = (i >> 2) & 31, mt = (i >> 7) & 15, kt = (i >> 11) & 15, l = i >> 15;
        int g = lane >> 2, t = lane & 3;
        int row = mt * 16 + g + (reg & 1) * 8;
        int col = kt * 16 + 2 * t + (reg >> 1) * 8;
        const float* W = (l == 0) ? W1 : ((l == 1) ? W2 : W3);
        __half lo = __float2half_rn(W[row * 256 + col]);
        __half hi = __float2half_rn(W[row * 256 + col + 1]);
        g_Wh[i] = (uint32_t)__half_as_ushort(lo) | ((uint32_t)__half_as_ushort(hi) << 16);
    } else if (blockIdx.x < 1216) {    // U/V tables
        int i = (blockIdx.x - 192) * 512 + threadIdx.x;
        int w = i & 63, o = (i >> 6) & 255, b = i >> 14;
        const float* xb = x + (size_t)b * 4096 + w;
        const float* w1 = W1 + (size_t)o * 256;
        float u = 0.f, v = 0.f;
        #pragma unroll 8
        for (int c = 0; c < 64; c++) {
            float xv = xb[c * 64];
            u = fmaf(w1[128 + c], xv, u);
            v = fmaf(w1[192 + c], xv, v);
        }
        g_U[i] = u; g_V[i] = v;
    } else {                            // W -> fp32 transposed [l][k][o]
        int i = (blockIdx.x - 1216) * 512 + threadIdx.x;   // 49152 threads
        int o = i & 255, k4 = (i >> 8) & 63, l = i >> 14;
        const float* W = (l == 0) ? W1 : ((l == 1) ? W2 : W3);
        float4 w = *(const float4*)(W + o * 256 + 4 * k4);
        float* d = g_WtT + (size_t)l * 65536 + o;
        d[(4 * k4 + 0) * 256] = w.x; d[(4 * k4 + 1) * 256] = w.y;
        d[(4 * k4 + 2) * 256] = w.z; d[(4 * k4 + 3) * 256] = w.w;
    }
}

__device__ __forceinline__ void mma_f16(float* d, const uint32_t* a, const uint32_t* b) {
    asm volatile(
        "mma.sync.aligned.m16n8k16.row.col.f32.f16.f16.f32 "
        "{%0,%1,%2,%3}, {%4,%5,%6,%7}, {%8,%9}, {%0,%1,%2,%3};"
        : "+f"(d[0]), "+f"(d[1]), "+f"(d[2]), "+f"(d[3])
        : "r"(a[0]), "r"(a[1]), "r"(a[2]), "r"(a[3]), "r"(b[0]), "r"(b[1]));
}
#define BAR_MMA() asm volatile("bar.sync 0, 384;" ::: "memory")

// 512 threads: warps 0-11 = MMA (96 positions, 4m x 3n), warps 12-15 = FFMA (16 positions).
__global__ __launch_bounds__(512, 1) void fused_kernel(
    const float* __restrict__ x, const float* __restrict__ xc,
    const float* __restrict__ b1, const float* __restrict__ b2,
    const float* __restrict__ b3, float* __restrict__ out)
{
    extern __shared__ uint32_t actU[];
    char* const sc = (char*)actU;
    float* const Us = (float*)(sc + SM_UV);
    float* const Vs = Us + 256 * UVSTRIDE;
    float* const bA = (float*)(sc + SM_BUFA);
    float* const bB = (float*)(sc + SM_BUFB);
    const int tid = threadIdx.x, lane = tid & 31, wid = tid >> 5;
    const int g = lane >> 2, t = lane & 3;
    const int b = blockIdx.x / TPB, q0 = (blockIdx.x % TPB) * NPOS;

    {   // UV staging
        const float* Ug = g_U + (size_t)b * 16384;
        const float* Vg = g_V + (size_t)b * 16384;
        for (int idx = tid; idx < 16384; idx += 512) {
            int o = idx >> 6, w = idx & 63;
            Us[o * UVSTRIDE + w] = Ug[idx];
            Vs[o * UVSTRIDE + w] = Vg[idx];
        }
    }
    // fp16 fragments for MMA positions (128 ch x 96 pos)
    for (int idx = tid; idx < 128 * PMMA; idx += 512) {
        int k = idx / PMMA, j = idx - k * PMMA;
        *(__half*)(sc + faddr16(k, j)) =
            __float2half_rn(xc[(size_t)(b * 128 + k) * 4032 + q0 + j]);
    }
    // fp32 xc for FFMA positions (128 ch x 16 pos) into bufB
    for (int idx = tid; idx < 2048; idx += 512) {
        int k = idx >> 4, p = idx & 15;
        bB[k * FSTRIDE + p] = xc[(size_t)(b * 128 + k) * 4032 + q0 + 96 + p];
    }
    __syncthreads();

    if (wid < 12) {   // ================= MMA group =================
        const int wm = wid & 3, wn = wid >> 2;
        const float* biases[3] = {b1, b2, b3};
        for (int l = 0; l < 3; l++) {
            float acc[4][4][4];
            #pragma unroll
            for (int mt = 0; mt < 4; mt++)
                #pragma unroll
                for (int nt = 0; nt < 4; nt++)
                    #pragma unroll
                    for (int r = 0; r < 4; r++) acc[mt][nt][r] = 0.f;
            const uint4* Ab = (const uint4*)g_Wh + (size_t)l * 8192 + lane;
            const uint2* Bb = (const uint2*)actU + lane;
            const int ktn = (l == 0) ? 8 : 16;
            #pragma unroll 4
            for (int kt = 0; kt < ktn; kt++) {
                uint32_t Br[4][2];
                #pragma unroll
                for (int nt = 0; nt < 4; nt++) {
                    uint2 bv = Bb[(kt * NTILES + wn * 4 + nt) * 32];
                    Br[nt][0] = bv.x; Br[nt][1] = bv.y;
                }
                #pragma unroll
                for (int mt = 0; mt < 4; mt++) {
                    uint4 av = Ab[(kt * 16 + wm * 4 + mt) * 32];
                    uint32_t Ar[4] = {av.x, av.y, av.z, av.w};
                    #pragma unroll
                    for (int nt = 0; nt < 4; nt++) mma_f16(acc[mt][nt], Ar, Br[nt]);
                }
            }
            BAR_MMA();
            const float* bl = biases[l];
            #pragma unroll
            for (int mt = 0; mt < 4; mt++) {
                const int R0 = (wm * 4 + mt) * 16 + g;
                const float bb0 = bl[R0], bb8 = bl[R0 + 8];
                if (l == 0) {
                    const float* U0 = Us + R0 * UVSTRIDE;
                    const float* V0 = Vs + R0 * UVSTRIDE;
                    #pragma unroll
                    for (int nt = 0; nt < 4; nt++) {
                        const int C0 = wn * 32 + nt * 8 + 2 * t;
                        const int qa = q0 + C0, qb2 = qa + 1;
                        const int wa = qa & 63, ja = (wa - (qa >> 6) - 1) & 63;
                        const int wb = qb2 & 63, jb = (wb - (qb2 >> 6) - 1) & 63;
                        *(__half*)(sc + faddr16(R0, C0)) = __float2half_rn(
                            fmaxf(acc[mt][nt][0] + U0[wa] + V0[ja] + bb0, 0.f));
                        *(__half*)(sc + faddr16(R0, C0 + 1)) = __float2half_rn(
                            fmaxf(acc[mt][nt][1] + U0[wb] + V0[jb] + bb0, 0.f));
                        *(__half*)(sc + faddr16(R0 + 8, C0)) = __float2half_rn(
                            fmaxf(acc[mt][nt][2] + U0[8*UVSTRIDE+wa] + V0[8*UVSTRIDE+ja] + bb8, 0.f));
                        *(__half*)(sc + faddr16(R0 + 8, C0 + 1)) = __float2half_rn(
                            fmaxf(acc[mt][nt][3] + U0[8*UVSTRIDE+wb] + V0[8*UVSTRIDE+jb] + bb8, 0.f));
                    }
                } else if (l == 1) {
                    #pragma unroll
                    for (int nt = 0; nt < 4; nt++) {
                        const int C0 = wn * 32 + nt * 8 + 2 * t;
                        *(__half*)(sc + faddr16(R0, C0)) = __float2half_rn(fmaxf(acc[mt][nt][0] + bb0, 0.f));
                        *(__half*)(sc + faddr16(R0, C0 + 1)) = __float2half_rn(fmaxf(acc[mt][nt][1] + bb0, 0.f));
                        *(__half*)(sc + faddr16(R0 + 8, C0)) = __float2half_rn(fmaxf(acc[mt][nt][2] + bb8, 0.f));
                        *(__half*)(sc + faddr16(R0 + 8, C0 + 1)) = __float2half_rn(fmaxf(acc[mt][nt][3] + bb8, 0.f));
                    }
                } else {
                    float* p0 = out + ((size_t)(b * 256 + R0)) * 4032 + q0;
                    float* p8 = p0 + (size_t)8 * 4032;
                    #pragma unroll
                    for (int nt = 0; nt < 4; nt++) {
                        const int C0 = wn * 32 + nt * 8 + 2 * t;
                        *(float2*)(p0 + C0) = make_float2(fmaxf(acc[mt][nt][0] + bb0, 0.f),
                                                          fmaxf(acc[mt][nt][1] + bb0, 0.f));
                        *(float2*)(p8 + C0) = make_float2(fmaxf(acc[mt][nt][2] + bb8, 0.f),
                                                          fmaxf(acc[mt][nt][3] + bb8, 0.f));
                    }
                }
            }
            if (l < 2) BAR_MMA();
        }
    } else {          // ================= FFMA group =================
        const int p4 = (wid - 12) * 4;
        const int qb = q0 + 96 + p4;
        for (int l = 0; l < 3; l++) {
            const float* Wt = g_WtT + (size_t)l * 65536 + lane;
            const float* rb = (l == 1) ? bA : bB;    // l0: bufB(xc), l1: bufA, l2: bufB
            float* wb = (l == 0) ? bA : bB;
            const float* bl = (l == 0) ? b1 : ((l == 1) ? b2 : b3);
            const int K = l ? 256 : 128;
            float acc[8][4];
            #pragma unroll
            for (int j = 0; j < 8; j++)
                #pragma unroll
                for (int p = 0; p < 4; p++) acc[j][p] = 0.f;
            float4 ac = *(const float4*)(rb + p4);
            float wr[8];
            #pragma unroll
            for (int j = 0; j < 8; j++) wr[j] = Wt[32 * j];
            #pragma unroll 2
            for (int k = 0; k < K; k++) {
                float4 an = ac; float wn2[8];
                #pragma unroll
                for (int j = 0; j < 8; j++) wn2[j] = wr[j];
                if (k + 1 < K) {
                    an = *(const float4*)(rb + (k + 1) * FSTRIDE + p4);
                    #pragma unroll
                    for (int j = 0; j < 8; j++) wn2[j] = Wt[(k + 1) * 256 + 32 * j];
                }
                #pragma unroll
                for (int j = 0; j < 8; j++) {
                    acc[j][0] = fmaf(wr[j], ac.x, acc[j][0]);
                    acc[j][1] = fmaf(wr[j], ac.y, acc[j][1]);
                    acc[j][2] = fmaf(wr[j], ac.z, acc[j][2]);
                    acc[j][3] = fmaf(wr[j], ac.w, acc[j][3]);
                }
                ac = an;
                #pragma unroll
                for (int j = 0; j < 8; j++) wr[j] = wn2[j];
            }
            if (l < 2) {
                #pragma unroll
                for (int j = 0; j < 8; j++) {
                    const int o = lane + 32 * j;
                    const float bv = bl[o];
                    #pragma unroll
                    for (int p = 0; p < 4; p++) {
                        float v = acc[j][p] + bv;
                        if (l == 0) {
                            const int q = qb + p, w = q & 63;
                            const int jr = (w - (q >> 6) - 1) & 63;
                            v += Us[o * UVSTRIDE + w] + Vs[o * UVSTRIDE + jr];
                        }
                        wb[o * FSTRIDE + p4 + p] = fmaxf(v, 0.f);
                    }
                }
                __syncwarp();
            } else {
                #pragma unroll
                for (int j = 0; j < 8; j++) {
                    const int o = lane + 32 * j;
                    const float bv = bl[o];
                    float4 v;
                    v.x = fmaxf(acc[j][0] + bv, 0.f);
                    v.y = fmaxf(acc[j][1] + bv, 0.f);
                    v.z = fmaxf(acc[j][2] + bv, 0.f);
                    v.w = fmaxf(acc[j][3] + bv, 0.f);
                    *(float4*)(out + ((size_t)(b * 256 + o)) * 4032 + qb) = v;
                }
            }
        }
    }
}

extern "C" void kernel_launch(void* const* d_in, const int* in_sizes, int n_in,
                              void* d_out, int out_size) {
    const float* x = nullptr; const float* xc = nullptr;
    const float* Ws[3] = {nullptr, nullptr, nullptr};
    const float* Bs[3] = {nullptr, nullptr, nullptr};
    int wi = 0, bi = 0;
    for (int i = 0; i < n_in; i++) {
        int sz = in_sizes[i];
        if (sz == 32 * 64 * 64)              x = (const float*)d_in[i];
        else if (sz == 32 * 128 * 63 * 64)   xc = (const float*)d_in[i];
        else if (sz == 256 * 256 && wi < 3)  Ws[wi++] = (const float*)d_in[i];
        else if (sz == 256 && bi < 3)        Bs[bi++] = (const float*)d_in[i];
    }
    prologue_kernel<<<1312, 512>>>(x, Ws[0], Ws[1], Ws[2]);
    cudaFuncSetAttribute(fused_kernel,
                         cudaFuncAttributeMaxDynamicSharedMemorySize, SMEM_TOTAL);
    fused_kernel<<<32 * TPB, 512, SMEM_TOTAL>>>(x, xc, Bs[0], Bs[1], Bs[2], (float*)d_out);
}

// round 17
// speedup vs baseline: 1.8222x; 1.8222x over previous
#include <cuda_runtime.h>
#include <cuda_fp16.h>
#include <cstdint>

#define NPOS 112
#define TPB  36
#define PMMA 96
#define NTILES 12           // PMMA/8
#define SM_UV    49152      // fp16 fragment act buffer is [0, 49152)
#define UVSTRIDE 65
#define SM_BUFA  182272     // FFMA act buffers, 256 x FSTRIDE fp32 each
#define SM_BUFB  202752
#define FSTRIDE  20
#define SMEM_TOTAL 223232

__device__ __align__(1024) uint32_t g_Wh[3 * 32768];  // fp16 MMA fragments
__device__ float g_U[32 * 256 * 64];
__device__ float g_V[32 * 256 * 64];
__device__ float g_WtT[3 * 65536];                    // fp32 W transposed [l][k][o]

__device__ __forceinline__ uint32_t faddr16(int k, int p) {
    return (((((uint32_t)(k >> 4) * NTILES + (p >> 3)) * 64
            + ((p & 7) * 4 + ((k >> 1) & 3)) * 2 + ((k >> 3) & 1)) << 2)
            + ((k & 1) << 1));
}

__global__ __launch_bounds__(512) void prologue_kernel(
    const float* __restrict__ x,
    const float* __restrict__ W1, const float* __restrict__ W2,
    const float* __restrict__ W3)
{
    if (blockIdx.x < 192) {            // W -> fp16 fragment-major
        int i = blockIdx.x * 512 + threadIdx.x;
        int reg = i & 3, lane = (i >> 2) & 31, mt = (i >> 7) & 15, kt = (i >> 11) & 15, l = i >> 15;
        int g = lane >> 2, t = lane & 3;
        int row = mt * 16 + g + (reg & 1) * 8;
        int col = kt * 16 + 2 * t + (reg >> 1) * 8;
        const float* W = (l == 0) ? W1 : ((l == 1) ? W2 : W3);
        __half lo = __float2half_rn(W[row * 256 + col]);
        __half hi = __float2half_rn(W[row * 256 + col + 1]);
        g_Wh[i] = (uint32_t)__half_as_ushort(lo) | ((uint32_t)__half_as_ushort(hi) << 16);
    } else if (blockIdx.x < 1216) {    // U/V tables
        int i = (blockIdx.x - 192) * 512 + threadIdx.x;
        int w = i & 63, o = (i >> 6) & 255, b = i >> 14;
        const float* xb = x + (size_t)b * 4096 + w;
        const float* w1 = W1 + (size_t)o * 256;
        float u = 0.f, v = 0.f;
        #pragma unroll 8
        for (int c = 0; c < 64; c++) {
            float xv = xb[c * 64];
            u = fmaf(w1[128 + c], xv, u);
            v = fmaf(w1[192 + c], xv, v);
        }
        g_U[i] = u; g_V[i] = v;
    } else {                            // W -> fp32 transposed [l][k][o]
        int i = (blockIdx.x - 1216) * 512 + threadIdx.x;   // 49152 threads
        int o = i & 255, k4 = (i >> 8) & 63, l = i >> 14;
        const float* W = (l == 0) ? W1 : ((l == 1) ? W2 : W3);
        float4 w = *(const float4*)(W + o * 256 + 4 * k4);
        float* d = g_WtT + (size_t)l * 65536 + o;
        d[(4 * k4 + 0) * 256] = w.x; d[(4 * k4 + 1) * 256] = w.y;
        d[(4 * k4 + 2) * 256] = w.z; d[(4 * k4 + 3) * 256] = w.w;
    }
}

__device__ __forceinline__ void mma_f16(float* d, const uint32_t* a, const uint32_t* b) {
    asm volatile(
        "mma.sync.aligned.m16n8k16.row.col.f32.f16.f16.f32 "
        "{%0,%1,%2,%3}, {%4,%5,%6,%7}, {%8,%9}, {%0,%1,%2,%3};"
        : "+f"(d[0]), "+f"(d[1]), "+f"(d[2]), "+f"(d[3])
        : "r"(a[0]), "r"(a[1]), "r"(a[2]), "r"(a[3]), "r"(b[0]), "r"(b[1]));
}
#define BAR_MMA() asm volatile("bar.sync 0, 384;" ::: "memory")

// 512 threads: warps 0-11 = MMA (96 positions, 4m x 3n), warps 12-15 = FFMA (16 positions).
__global__ __launch_bounds__(512, 1) void fused_kernel(
    const float* __restrict__ x, const float* __restrict__ xc,
    const float* __restrict__ b1, const float* __restrict__ b2,
    const float* __restrict__ b3, float* __restrict__ out)
{
    extern __shared__ uint32_t actU[];
    char* const sc = (char*)actU;
    float* const Us = (float*)(sc + SM_UV);
    float* const Vs = Us + 256 * UVSTRIDE;
    float* const bA = (float*)(sc + SM_BUFA);
    float* const bB = (float*)(sc + SM_BUFB);
    const int tid = threadIdx.x, lane = tid & 31, wid = tid >> 5;
    const int g = lane >> 2, t = lane & 3;
    const int b = blockIdx.x / TPB, q0 = (blockIdx.x % TPB) * NPOS;

    {   // UV staging
        const float* Ug = g_U + (size_t)b * 16384;
        const float* Vg = g_V + (size_t)b * 16384;
        for (int idx = tid; idx < 16384; idx += 512) {
            int o = idx >> 6, w = idx & 63;
            Us[o * UVSTRIDE + w] = Ug[idx];
            Vs[o * UVSTRIDE + w] = Vg[idx];
        }
    }
    // fp16 fragments for MMA positions (128 ch x 96 pos)
    for (int idx = tid; idx < 128 * PMMA; idx += 512) {
        int k = idx / PMMA, j = idx - k * PMMA;
        *(__half*)(sc + faddr16(k, j)) =
            __float2half_rn(xc[(size_t)(b * 128 + k) * 4032 + q0 + j]);
    }
    // fp32 xc for FFMA positions (128 ch x 16 pos) into bufB
    for (int idx = tid; idx < 2048; idx += 512) {
        int k = idx >> 4, p = idx & 15;
        bB[k * FSTRIDE + p] = xc[(size_t)(b * 128 + k) * 4032 + q0 + 96 + p];
    }
    __syncthreads();

    if (wid < 12) {   // ================= MMA group =================
        const int wm = wid & 3, wn = wid >> 2;
        const float* biases[3] = {b1, b2, b3};
        for (int l = 0; l < 3; l++) {
            float acc[4][4][4];
            #pragma unroll
            for (int mt = 0; mt < 4; mt++)
                #pragma unroll
                for (int nt = 0; nt < 4; nt++)
                    #pragma unroll
                    for (int r = 0; r < 4; r++) acc[mt][nt][r] = 0.f;
            const uint4* Ab = (const uint4*)g_Wh + (size_t)l * 8192 + lane;
            const uint2* Bb = (const uint2*)actU + lane;
            const int ktn = (l == 0) ? 8 : 16;
            #pragma unroll 4
            for (int kt = 0; kt < ktn; kt++) {
                uint32_t Br[4][2];
                #pragma unroll
                for (int nt = 0; nt < 4; nt++) {
                    uint2 bv = Bb[(kt * NTILES + wn * 4 + nt) * 32];
                    Br[nt][0] = bv.x; Br[nt][1] = bv.y;
                }
                #pragma unroll
                for (int mt = 0; mt < 4; mt++) {
                    uint4 av = Ab[(kt * 16 + wm * 4 + mt) * 32];
                    uint32_t Ar[4] = {av.x, av.y, av.z, av.w};
                    #pragma unroll
                    for (int nt = 0; nt < 4; nt++) mma_f16(acc[mt][nt], Ar, Br[nt]);
                }
            }
            BAR_MMA();
            const float* bl = biases[l];
            #pragma unroll
            for (int mt = 0; mt < 4; mt++) {
                const int R0 = (wm * 4 + mt) * 16 + g;
                const float bb0 = bl[R0], bb8 = bl[R0 + 8];
                if (l == 0) {
                    const float* U0 = Us + R0 * UVSTRIDE;
                    const float* V0 = Vs + R0 * UVSTRIDE;
                    #pragma unroll
                    for (int nt = 0; nt < 4; nt++) {
                        const int C0 = wn * 32 + nt * 8 + 2 * t;
                        const int qa = q0 + C0, qb2 = qa + 1;
                        const int wa = qa & 63, ja = (wa - (qa >> 6) - 1) & 63;
                        const int wb = qb2 & 63, jb = (wb - (qb2 >> 6) - 1) & 63;
                        *(__half*)(sc + faddr16(R0, C0)) = __float2half_rn(
                            fmaxf(acc[mt][nt][0] + U0[wa] + V0[ja] + bb0, 0.f));
                        *(__half*)(sc + faddr16(R0, C0 + 1)) = __float2half_rn(
                            fmaxf(acc[mt][nt][1] + U0[wb] + V0[jb] + bb0, 0.f));
                        *(__half*)(sc + faddr16(R0 + 8, C0)) = __float2half_rn(
                            fmaxf(acc[mt][nt][2] + U0[8*UVSTRIDE+wa] + V0[8*UVSTRIDE+ja] + bb8, 0.f));
                        *(__half*)(sc + faddr16(R0 + 8, C0 + 1)) = __float2half_rn(
                            fmaxf(acc[mt][nt][3] + U0[8*UVSTRIDE+wb] + V0[8*UVSTRIDE+jb] + bb8, 0.f));
                    }
                } else if (l == 1) {
                    #pragma unroll
                    for (int nt = 0; nt < 4; nt++) {
                        const int C0 = wn * 32 + nt * 8 + 2 * t;
                        *(__half*)(sc + faddr16(R0, C0)) = __float2half_rn(fmaxf(acc[mt][nt][0] + bb0, 0.f));
                        *(__half*)(sc + faddr16(R0, C0 + 1)) = __float2half_rn(fmaxf(acc[mt][nt][1] + bb0, 0.f));
                        *(__half*)(sc + faddr16(R0 + 8, C0)) = __float2half_rn(fmaxf(acc[mt][nt][2] + bb8, 0.f));
                        *(__half*)(sc + faddr16(R0 + 8, C0 + 1)) = __float2half_rn(fmaxf(acc[mt][nt][3] + bb8, 0.f));
                    }
                } else {
                    float* p0 = out + ((size_t)(b * 256 + R0)) * 4032 + q0;
                    float* p8 = p0 + (size_t)8 * 4032;
                    #pragma unroll
                    for (int nt = 0; nt < 4; nt++) {
                        const int C0 = wn * 32 + nt * 8 + 2 * t;
                        *(float2*)(p0 + C0) = make_float2(fmaxf(acc[mt][nt][0] + bb0, 0.f),
                                                          fmaxf(acc[mt][nt][1] + bb0, 0.f));
                        *(float2*)(p8 + C0) = make_float2(fmaxf(acc[mt][nt][2] + bb8, 0.f),
                                                          fmaxf(acc[mt][nt][3] + bb8, 0.f));
                    }
                }
            }
            if (l < 2) BAR_MMA();
        }
    } else {          // ================= FFMA group =================
        const int p4 = (wid - 12) * 4;
        const int qb = q0 + 96 + p4;
        for (int l = 0; l < 3; l++) {
            const float* Wt = g_WtT + (size_t)l * 65536 + lane;
            const float* rb = (l == 1) ? bA : bB;    // l0: bufB(xc), l1: bufA, l2: bufB
            float* wb = (l == 0) ? bA : bB;
            const float* bl = (l == 0) ? b1 : ((l == 1) ? b2 : b3);
            const int K = l ? 256 : 128;
            float acc[8][4];
            #pragma unroll
            for (int j = 0; j < 8; j++)
                #pragma unroll
                for (int p = 0; p < 4; p++) acc[j][p] = 0.f;
            // simple loop: broadcast LDS128 + 8 coalesced LDG per k; ptxas pipelines.
            #pragma unroll 4
            for (int k = 0; k < K; k++) {
                const float4 a = *(const float4*)(rb + k * FSTRIDE + p4);
                const float* wk = Wt + k * 256;
                #pragma unroll
                for (int j = 0; j < 8; j++) {
                    const float w = wk[32 * j];
                    acc[j][0] = fmaf(w, a.x, acc[j][0]);
                    acc[j][1] = fmaf(w, a.y, acc[j][1]);
                    acc[j][2] = fmaf(w, a.z, acc[j][2]);
                    acc[j][3] = fmaf(w, a.w, acc[j][3]);
                }
            }
            if (l < 2) {
                #pragma unroll
                for (int j = 0; j < 8; j++) {
                    const int o = lane + 32 * j;
                    const float bv = bl[o];
                    #pragma unroll
                    for (int p = 0; p < 4; p++) {
                        float v = acc[j][p] + bv;
                        if (l == 0) {
                            const int q = qb + p, w = q & 63;
                            const int jr = (w - (q >> 6) - 1) & 63;
                            v += Us[o * UVSTRIDE + w] + Vs[o * UVSTRIDE + jr];
                        }
                        wb[o * FSTRIDE + p4 + p] = fmaxf(v, 0.f);
                    }
                }
                __syncwarp();
            } else {
                #pragma unroll
                for (int j = 0; j < 8; j++) {
                    const int o = lane + 32 * j;
                    const float bv = bl[o];
                    float4 v;
                    v.x = fmaxf(acc[j][0] + bv, 0.f);
                    v.y = fmaxf(acc[j][1] + bv, 0.f);
                    v.z = fmaxf(acc[j][2] + bv, 0.f);
                    v.w = fmaxf(acc[j][3] + bv, 0.f);
                    *(float4*)(out + ((size_t)(b * 256 + o)) * 4032 + qb) = v;
                }
            }
        }
    }
}

extern "C" void kernel_launch(void* const* d_in, const int* in_sizes, int n_in,
                              void* d_out, int out_size) {
    const float* x = nullptr; const float* xc = nullptr;
    const float* Ws[3] = {nullptr, nullptr, nullptr};
    const float* Bs[3] = {nullptr, nullptr, nullptr};
    int wi = 0, bi = 0;
    for (int i = 0; i < n_in; i++) {
        int sz = in_sizes[i];
        if (sz == 32 * 64 * 64)              x = (const float*)d_in[i];
        else if (sz == 32 * 128 * 63 * 64)   xc = (const float*)d_in[i];
        else if (sz == 256 * 256 && wi < 3)  Ws[wi++] = (const float*)d_in[i];
        else if (sz == 256 && bi < 3)        Bs[bi++] = (const float*)d_in[i];
    }
    prologue_kernel<<<1312, 512>>>(x, Ws[0], Ws[1], Ws[2]);
    cudaFuncSetAttribute(fused_kernel,
                         cudaFuncAttributeMaxDynamicSharedMemorySize, SMEM_TOTAL);
    fused_kernel<<<32 * TPB, 512, SMEM_TOTAL>>>(x, xc, Bs[0], Bs[1], Bs[2], (float*)d_out);
}